// round 15
// baseline (speedup 1.0000x reference)
#include <cuda_runtime.h>
#include <cuda_fp16.h>
#include <math.h>
#include <stdint.h>

// Problem constants
#define B_   4
#define S_   1024
#define E_   1024
#define D_   1024
#define H_   16
#define DH_  64
#define DFF_ 4096
#define MROWS (B_*S_)   // 4096

__device__ __forceinline__ uint32_t smem_u32(const void* p) {
    uint32_t a;
    asm("{ .reg .u64 t; cvta.to.shared.u64 t, %1; cvt.u32.u64 %0, t; }"
        : "=r"(a) : "l"(p));
    return a;
}

// ============================= scratch =====================================
__device__ float  g_tmp   [(size_t)MROWS * D_];
__device__ float  g_h1    [(size_t)MROWS * D_];
__device__ float  g_h2    [(size_t)MROWS * D_];

__device__ __half g_x16   [(size_t)MROWS * D_];
__device__ __half g_ex16  [(size_t)B_ * E_ * D_];
__device__ __half g_qkv16 [(size_t)MROWS * 3 * D_];
__device__ __half g_attn16[(size_t)MROWS * D_];
__device__ __half g_h16   [(size_t)MROWS * D_];
__device__ __half g_q16   [(size_t)MROWS * D_];
__device__ __half g_k16   [(size_t)B_ * E_ * D_];
__device__ __half g_v16   [(size_t)B_ * E_ * D_];
__device__ __half g_f116  [(size_t)MROWS * DFF_];
// V transposed to [bh][dh][S] for trans-free PV fragments
__device__ __half g_vts   [(size_t)B_ * H_ * DH_ * S_];
__device__ __half g_vt    [(size_t)B_ * H_ * DH_ * S_];
__device__ __half g_wqkvT [(size_t)3 * D_ * D_];
__device__ __half g_wsaoT [(size_t)D_ * D_];
__device__ __half g_wqT   [(size_t)D_ * D_];
__device__ __half g_wkT   [(size_t)D_ * D_];
__device__ __half g_wvT   [(size_t)D_ * D_];
__device__ __half g_wcaoT [(size_t)D_ * D_];
__device__ __half g_w1T   [(size_t)D_ * DFF_];
__device__ __half g_w2T   [(size_t)DFF_ * D_];

// ==================== fused prep: all transposes + converts ================
#define PREP_BLOCKS 18432

__global__ __launch_bounds__(1024)
void prep_kernel(const float* __restrict__ w_qkv, const float* __restrict__ w_sa_o,
                 const float* __restrict__ w_q,  const float* __restrict__ w_k,
                 const float* __restrict__ w_v,  const float* __restrict__ w_ca_o,
                 const float* __restrict__ w1,   const float* __restrict__ w2,
                 const float* __restrict__ x,    const float* __restrict__ enc_x,
                 __half* __restrict__ wqkvT, __half* __restrict__ wsaoT,
                 __half* __restrict__ wqT,   __half* __restrict__ wkT,
                 __half* __restrict__ wvT,   __half* __restrict__ wcaoT,
                 __half* __restrict__ w1T,   __half* __restrict__ w2T,
                 __half* __restrict__ x16,   __half* __restrict__ ex16)
{
    const int bid = blockIdx.x;
    const int tx = threadIdx.x & 31;
    const int ty = threadIdx.x >> 5;

    const float* src; __half* dst; int K, N, tile, nx;
    if (bid < 16384) {
        if (bid < 3072)       { src = w_qkv;  dst = wqkvT; K = D_;   N = 3 * D_; tile = bid;         nx = 96;  }
        else if (bid < 4096)  { src = w_sa_o; dst = wsaoT; K = D_;   N = D_;     tile = bid - 3072;  nx = 32;  }
        else if (bid < 5120)  { src = w_q;    dst = wqT;   K = D_;   N = D_;     tile = bid - 4096;  nx = 32;  }
        else if (bid < 6144)  { src = w_k;    dst = wkT;   K = D_;   N = D_;     tile = bid - 5120;  nx = 32;  }
        else if (bid < 7168)  { src = w_v;    dst = wvT;   K = D_;   N = D_;     tile = bid - 6144;  nx = 32;  }
        else if (bid < 8192)  { src = w_ca_o; dst = wcaoT; K = D_;   N = D_;     tile = bid - 7168;  nx = 32;  }
        else if (bid < 12288) { src = w1;     dst = w1T;   K = D_;   N = DFF_;   tile = bid - 8192;  nx = 128; }
        else                  { src = w2;     dst = w2T;   K = DFF_; N = D_;     tile = bid - 12288; nx = 32;  }

        __shared__ float t[32][33];
        const int bx = tile % nx, by = tile / nx;
        int k = by * 32 + ty;
        int n = bx * 32 + tx;
        t[ty][tx] = src[(size_t)k * N + n];
        __syncthreads();
        int nn = bx * 32 + ty;
        int kk = by * 32 + tx;
        dst[(size_t)nn * K + kk] = __float2half(t[tx][ty]);
    } else {
        const int cb = bid - 16384;
        const float4* in;
        __half2* out;
        int base;
        if (cb < 1024) { in = (const float4*)x;     out = (__half2*)x16;  base = cb; }
        else           { in = (const float4*)enc_x; out = (__half2*)ex16; base = cb - 1024; }
        int i = base * 1024 + (int)threadIdx.x;
        float4 v = in[i];
        out[2 * i]     = __floats2half2_rn(v.x, v.y);
        out[2 * i + 1] = __floats2half2_rn(v.z, v.w);
    }
}

// ======== V transpose: [s][h*hs+add+d] -> [bh][d][s]  (self + cross) =======
// 8192 blocks: 0..4095 self (qkv16, hs=192, add=128), 4096..8191 cross (v16)
__global__ __launch_bounds__(256)
void vtrans_kernel(const __half* __restrict__ qkv, const __half* __restrict__ v,
                   __half* __restrict__ vts, __half* __restrict__ vt)
{
    __shared__ __half t[32][33];
    int bid = blockIdx.x;
    const __half* src; __half* dst; int rs, hs, add;
    if (bid < 4096) { src = qkv; dst = vts; rs = 3 * D_; hs = 192; add = 128; }
    else            { src = v;   dst = vt;  rs = D_;     hs = 64;  add = 0; bid -= 4096; }
    const int kt = bid & 31;
    const int dt = (bid >> 5) & 1;
    const int bh = bid >> 6;
    const int b = bh >> 4, h = bh & 15;
    const int tx = threadIdx.x & 31, ty0 = threadIdx.x >> 5;
    #pragma unroll
    for (int i = 0; i < 4; i++) {
        int ty = ty0 + i * 8;   // k-row within tile
        t[ty][tx] = src[(size_t)(b * S_ + kt * 32 + ty) * rs + h * hs + add + dt * 32 + tx];
    }
    __syncthreads();
    #pragma unroll
    for (int i = 0; i < 4; i++) {
        int ty = ty0 + i * 8;   // d-row within tile
        dst[(size_t)(bh * 64 + dt * 32 + ty) * S_ + kt * 32 + tx] = t[tx][ty];
    }
}

// ========================= mma primitives ==================================
__device__ __forceinline__ void ldmx4(uint32_t* r, uint32_t addr) {
    asm volatile("ldmatrix.sync.aligned.m8n8.x4.shared.b16 {%0,%1,%2,%3}, [%4];"
                 : "=r"(r[0]), "=r"(r[1]), "=r"(r[2]), "=r"(r[3]) : "r"(addr));
}
__device__ __forceinline__ void mma16816(float* c, const uint32_t* a, const uint32_t* b) {
    asm volatile("mma.sync.aligned.m16n8k16.row.col.f32.f16.f16.f32 "
                 "{%0,%1,%2,%3}, {%4,%5,%6,%7}, {%8,%9}, {%0,%1,%2,%3};"
                 : "+f"(c[0]), "+f"(c[1]), "+f"(c[2]), "+f"(c[3])
                 : "r"(a[0]), "r"(a[1]), "r"(a[2]), "r"(a[3]), "r"(b[0]), "r"(b[1]));
}
#define CP_ASYNC16(smem, gmem) \
    asm volatile("cp.async.cg.shared.global [%0], [%1], 16;" \
                 :: "r"(smem), "l"(gmem) : "memory")
#define CP_COMMIT() asm volatile("cp.async.commit_group;" ::: "memory")
#define CP_WAIT0()  asm volatile("cp.async.wait_group 0;" ::: "memory")
#define CP_WAIT1()  asm volatile("cp.async.wait_group 1;" ::: "memory")

// ===================== mma.sync fp16 GEMM body =============================
// CTA tile 128x256x32, 8 warps (2m x 4n), warp tile 64x64.
// 3-stage cp.async ring + register fragment double-buffering.
#define TM 128
#define TN 256
#define KC 32
#define PAD 40
#define A_STAGE (TM * PAD * 2)               // 10240 B
#define B_STAGE (TN * PAD * 2)               // 20480 B
#define GEMM_SMEM (3 * (A_STAGE + B_STAGE))  // 92160 B

__device__ __forceinline__ void gemm_body(
    const __half* __restrict__ A, const __half* __restrict__ Bt,
    const float* __restrict__ bias, float* __restrict__ outf,
    __half* __restrict__ outh, int N, int K, int act,
    int m0, int n0, uint32_t sbase)
{
    #define SA_ADDR(st, r, c) (sbase + (uint32_t)(st) * A_STAGE + (uint32_t)((r) * PAD + (c)) * 2)
    #define SB_ADDR(st, r, c) (sbase + 3u * A_STAGE + (uint32_t)(st) * B_STAGE + (uint32_t)((r) * PAD + (c)) * 2)

    const int tid  = threadIdx.x;
    const int lane = tid & 31;
    const int wid  = tid >> 5;
    const int wm   = wid & 1;
    const int wn   = wid >> 1;

    float acc[4][8][4];
    #pragma unroll
    for (int i = 0; i < 4; i++)
        #pragma unroll
        for (int j = 0; j < 8; j++)
            #pragma unroll
            for (int q = 0; q < 4; q++) acc[i][j][q] = 0.f;

    const int r0c = tid >> 1;
    const int j0c = (tid & 1) * 2;
    const int nch = K / KC;

    #define ISSUE_CHUNK(cc_, stg_) do {                                              \
        const __half* Ag_ = A  + (size_t)m0 * K + (cc_) * KC;                        \
        const __half* Bg_ = Bt + (size_t)n0 * K + (cc_) * KC;                        \
        _Pragma("unroll")                                                            \
        for (int j = 0; j < 2; j++)                                                  \
            CP_ASYNC16(SA_ADDR(stg_, r0c, (j0c + j) * 8), Ag_ + (size_t)r0c * K + (j0c + j) * 8); \
        _Pragma("unroll")                                                            \
        for (int h = 0; h < 2; h++) {                                                \
            int rb_ = r0c + h * 128;                                                 \
            _Pragma("unroll")                                                        \
            for (int j = 0; j < 2; j++)                                              \
                CP_ASYNC16(SB_ADDR(stg_, rb_, (j0c + j) * 8), Bg_ + (size_t)rb_ * K + (j0c + j) * 8); \
        }                                                                            \
    } while (0)

    #define LDFRAGS(stg_, ks_, AF, BF) do {                                          \
        _Pragma("unroll")                                                            \
        for (int mi = 0; mi < 4; mi++) {                                             \
            int r_  = wm * 64 + mi * 16 + (lane & 15);                               \
            int cc_ = (ks_) * 16 + ((lane >> 4) << 3);                               \
            ldmx4((AF)[mi], SA_ADDR(stg_, r_, cc_));                                 \
        }                                                                            \
        _Pragma("unroll")                                                            \
        for (int nj = 0; nj < 4; nj++) {                                             \
            int r_  = wn * 64 + nj * 16 + ((lane & 7) | ((lane & 16) >> 1));         \
            int cc_ = (ks_) * 16 + (((lane >> 3) & 1) << 3);                         \
            ldmx4((BF)[nj], SB_ADDR(stg_, r_, cc_));                                 \
        }                                                                            \
    } while (0)

    #define MMASET(AF, BF) do {                                                      \
        _Pragma("unroll")                                                            \
        for (int mi = 0; mi < 4; mi++)                                               \
            _Pragma("unroll")                                                        \
            for (int nj = 0; nj < 8; nj++)                                           \
                mma16816(acc[mi][nj], (AF)[mi], &(BF)[nj >> 1][(nj & 1) * 2]);       \
    } while (0)

    ISSUE_CHUNK(0, 0); CP_COMMIT();
    ISSUE_CHUNK(1, 1); CP_COMMIT();
    CP_WAIT1();
    __syncthreads();

    uint32_t afr0[4][4], bfr0[4][4], afr1[4][4], bfr1[4][4];
    LDFRAGS(0, 0, afr0, bfr0);

    int st = 0, stw = 2;
    for (int c = 0; c < nch; c++) {
        if (c + 2 < nch) ISSUE_CHUNK(c + 2, stw);
        CP_COMMIT();

        LDFRAGS(st, 1, afr1, bfr1);
        MMASET(afr0, bfr0);

        if (c + 1 < nch) {
            CP_WAIT1();
            __syncthreads();
            const int nst = (st == 2) ? 0 : st + 1;
            LDFRAGS(nst, 0, afr0, bfr0);
        }
        MMASET(afr1, bfr1);

        st  = (st  == 2) ? 0 : st  + 1;
        stw = (stw == 2) ? 0 : stw + 1;
    }

    #pragma unroll
    for (int mi = 0; mi < 4; mi++) {
        #pragma unroll
        for (int rr = 0; rr < 2; rr++) {
            const int row = m0 + wm * 64 + mi * 16 + rr * 8 + (lane >> 2);
            #pragma unroll
            for (int nj = 0; nj < 8; nj++) {
                const int col = n0 + wn * 64 + nj * 8 + (lane & 3) * 2;
                float v0 = acc[mi][nj][rr * 2 + 0] + bias[col];
                float v1 = acc[mi][nj][rr * 2 + 1] + bias[col + 1];
                if (act) {
                    v0 = 0.5f * v0 * (1.0f + erff(v0 * 0.70710678118654752f));
                    v1 = 0.5f * v1 * (1.0f + erff(v1 * 0.70710678118654752f));
                }
                if (outf)
                    *(float2*)(outf + (size_t)row * N + col) = make_float2(v0, v1);
                if (outh)
                    *(__half2*)(outh + (size_t)row * N + col) = __floats2half2_rn(v0, v1);
            }
        }
    }
    #undef SA_ADDR
    #undef SB_ADDR
    #undef ISSUE_CHUNK
    #undef LDFRAGS
    #undef MMASET
}

__global__ void __launch_bounds__(256)
gemm_tc(const __half* __restrict__ A, const __half* __restrict__ Bt,
        const float* __restrict__ bias, float* __restrict__ outf,
        __half* __restrict__ outh, int M, int N, int K, int act)
{
    extern __shared__ char dynsm[];
    gemm_body(A, Bt, bias, outf, outh, N, K, act,
              blockIdx.y * TM, blockIdx.x * TN, smem_u32(dynsm));
}

__global__ void __launch_bounds__(256)
gemm3_tc(const __half* __restrict__ A0, const __half* __restrict__ A12,
         const __half* __restrict__ W0, const __half* __restrict__ W1,
         const __half* __restrict__ W2,
         const float* __restrict__ b0, const float* __restrict__ b1,
         const float* __restrict__ b2,
         __half* __restrict__ o0, __half* __restrict__ o1, __half* __restrict__ o2)
{
    extern __shared__ char dynsm[];
    const int bx = blockIdx.x;
    const __half *A, *W; const float* bias; __half* outh; int N, n0;
    if (bx < 12)      { A = A0;  W = W0; bias = b0; outh = o0; N = 3 * D_; n0 = bx * TN; }
    else if (bx < 16) { A = A12; W = W1; bias = b1; outh = o1; N = D_;     n0 = (bx - 12) * TN; }
    else              { A = A12; W = W2; bias = b2; outh = o2; N = D_;     n0 = (bx - 16) * TN; }
    gemm_body(A, W, bias, (float*)0, outh, N, D_, 0,
              blockIdx.y * TM, n0, smem_u32(dynsm));
}

// ================= fused flash attention (fp16 mma) ========================
// V supplied pre-transposed: VT[bh][dh=64][S]. PV B-frags use non-trans ldmx4.
__global__ void __launch_bounds__(128)
flash_kernel(const __half* __restrict__ Qp, const __half* __restrict__ Kp,
             const __half* __restrict__ VT, __half* __restrict__ Op,
             int qrs, int krs, int qhs, int khs, int kadd, int causal)
{
    __shared__ __align__(16) __half sQ[64][72];
    __shared__ __align__(16) __half sK[2][64][72];
    __shared__ __align__(16) __half sV[2][64][72];   // [dh][kpos]

    const int tid  = threadIdx.x;
    const int lane = tid & 31;
    const int warp = tid >> 5;
    const int bh = blockIdx.y;
    const int b  = bh >> 4;
    const int h  = bh & 15;
    const int q0 = blockIdx.x * 64;

    const __half* Qb  = Qp + (size_t)(b * S_ + q0) * qrs + h * qhs;
    const __half* Kb  = Kp + (size_t)(b * S_) * krs + h * khs + kadd;
    const __half* VTb = VT + (size_t)bh * 64 * S_;

    const __half2 sc8 = __float2half2_rn(0.125f);
    #pragma unroll
    for (int i = 0; i < 4; i++) {
        int ch = tid + i * 128;
        int r = ch >> 3, j = ch & 7;
        uint4 u = *(const uint4*)(Qb + (size_t)r * qrs + j * 8);
        __half2* hp = (__half2*)&u;
        #pragma unroll
        for (int q = 0; q < 4; q++) hp[q] = __hmul2(hp[q], sc8);
        *(uint4*)&sQ[r][j * 8] = u;
    }
    #pragma unroll
    for (int i = 0; i < 4; i++) {
        int ch = tid + i * 128;
        int r = ch >> 3, j = ch & 7;
        CP_ASYNC16(smem_u32(&sK[0][r][j * 8]), Kb + (size_t)r * krs + j * 8);
        CP_ASYNC16(smem_u32(&sV[0][r][j * 8]), VTb + (size_t)r * S_ + j * 8);
    }
    CP_COMMIT();

    uint32_t qf[4][4];
    float m0 = -1e30f, m1 = -1e30f, l0 = 0.f, l1 = 0.f;
    float o[8][4];
    #pragma unroll
    for (int nj = 0; nj < 8; nj++)
        #pragma unroll
        for (int q = 0; q < 4; q++) o[nj][q] = 0.f;

    const int nkt = causal ? (blockIdx.x + 1) : (S_ / 64);

    for (int kt = 0; kt < nkt; kt++) {
        CP_WAIT0();
        __syncthreads();

        if (kt == 0) {
            #pragma unroll
            for (int ks = 0; ks < 4; ks++) {
                int r  = warp * 16 + (lane & 15);
                int cc = ks * 16 + ((lane >> 4) << 3);
                ldmx4(qf[ks], smem_u32(&sQ[r][cc]));
            }
        }
        if (kt + 1 < nkt) {
            const int nb = (kt + 1) & 1;
            #pragma unroll
            for (int i = 0; i < 4; i++) {
                int ch = tid + i * 128;
                int r = ch >> 3, j = ch & 7;
                CP_ASYNC16(smem_u32(&sK[nb][r][j * 8]), Kb + (size_t)((kt + 1) * 64 + r) * krs + j * 8);
                CP_ASYNC16(smem_u32(&sV[nb][r][j * 8]), VTb + (size_t)r * S_ + (kt + 1) * 64 + j * 8);
            }
            CP_COMMIT();
        }
        const int cb = kt & 1;

        float s[8][4];
        #pragma unroll
        for (int nj = 0; nj < 8; nj++)
            #pragma unroll
            for (int q = 0; q < 4; q++) s[nj][q] = 0.f;

        #pragma unroll
        for (int ks = 0; ks < 4; ks++) {
            #pragma unroll
            for (int nj2 = 0; nj2 < 4; nj2++) {
                uint32_t bf[4];
                int r  = nj2 * 16 + ((lane & 7) | ((lane & 16) >> 1));
                int cc = ks * 16 + (((lane >> 3) & 1) << 3);
                ldmx4(bf, smem_u32(&sK[cb][r][cc]));
                mma16816(s[2 * nj2],     qf[ks], &bf[0]);
                mma16816(s[2 * nj2 + 1], qf[ks], &bf[2]);
            }
        }

        if (causal && kt == (int)blockIdx.x) {
            int rl = warp * 16 + (lane >> 2);
            int c0 = (lane & 3) * 2;
            #pragma unroll
            for (int nj = 0; nj < 8; nj++) {
                int k0l = nj * 8 + c0;
                if (k0l     > rl)     s[nj][0] = -1e30f;
                if (k0l + 1 > rl)     s[nj][1] = -1e30f;
                if (k0l     > rl + 8) s[nj][2] = -1e30f;
                if (k0l + 1 > rl + 8) s[nj][3] = -1e30f;
            }
        }

        float mx0 = -1e30f, mx1 = -1e30f;
        #pragma unroll
        for (int nj = 0; nj < 8; nj++) {
            mx0 = fmaxf(mx0, fmaxf(s[nj][0], s[nj][1]));
            mx1 = fmaxf(mx1, fmaxf(s[nj][2], s[nj][3]));
        }
        mx0 = fmaxf(mx0, __shfl_xor_sync(~0u, mx0, 1));
        mx0 = fmaxf(mx0, __shfl_xor_sync(~0u, mx0, 2));
        mx1 = fmaxf(mx1, __shfl_xor_sync(~0u, mx1, 1));
        mx1 = fmaxf(mx1, __shfl_xor_sync(~0u, mx1, 2));

        float nm0 = fmaxf(m0, mx0), nm1 = fmaxf(m1, mx1);
        float sc0 = __expf(m0 - nm0), sc1 = __expf(m1 - nm1);
        m0 = nm0; m1 = nm1;
        l0 *= sc0; l1 *= sc1;
        #pragma unroll
        for (int nj = 0; nj < 8; nj++) {
            o[nj][0] *= sc0; o[nj][1] *= sc0;
            o[nj][2] *= sc1; o[nj][3] *= sc1;
        }

        uint32_t pk[8][2];
        float rs0 = 0.f, rs1 = 0.f;
        #pragma unroll
        for (int nj = 0; nj < 8; nj++) {
            float p0 = __expf(s[nj][0] - m0), p1 = __expf(s[nj][1] - m0);
            float p2 = __expf(s[nj][2] - m1), p3 = __expf(s[nj][3] - m1);
            rs0 += p0 + p1; rs1 += p2 + p3;
            __half2 hA = __floats2half2_rn(p0, p1);
            __half2 hB = __floats2half2_rn(p2, p3);
            pk[nj][0] = *(uint32_t*)&hA;
            pk[nj][1] = *(uint32_t*)&hB;
        }
        l0 += rs0; l1 += rs1;

        // O += P @ V   (B-frags: non-trans ldmx4 on [dh][kpos] tile)
        #pragma unroll
        for (int t = 0; t < 4; t++) {
            uint32_t a[4] = { pk[2 * t][0], pk[2 * t][1], pk[2 * t + 1][0], pk[2 * t + 1][1] };
            #pragma unroll
            for (int nj2 = 0; nj2 < 4; nj2++) {
                uint32_t bf[4];
                int r  = nj2 * 16 + ((lane & 7) | ((lane & 16) >> 1));
                int cc = t * 16 + (((lane >> 3) & 1) << 3);
                ldmx4(bf, smem_u32(&sV[cb][r][cc]));
                mma16816(o[2 * nj2],     a, &bf[0]);
                mma16816(o[2 * nj2 + 1], a, &bf[2]);
            }
        }
    }

    l0 += __shfl_xor_sync(~0u, l0, 1);
    l0 += __shfl_xor_sync(~0u, l0, 2);
    l1 += __shfl_xor_sync(~0u, l1, 1);
    l1 += __shfl_xor_sync(~0u, l1, 2);
    float inv0 = 1.f / l0, inv1 = 1.f / l1;

    const int row0 = q0 + warp * 16 + (lane >> 2);
    #pragma unroll
    for (int nj = 0; nj < 8; nj++) {
        int col = h * 64 + nj * 8 + (lane & 3) * 2;
        *(__half2*)(Op + (size_t)(b * S_ + row0) * D_ + col) =
            __floats2half2_rn(o[nj][0] * inv0, o[nj][1] * inv0);
        *(__half2*)(Op + (size_t)(b * S_ + row0 + 8) * D_ + col) =
            __floats2half2_rn(o[nj][2] * inv1, o[nj][3] * inv1);
    }
}

// ---------------- fused residual-add + LayerNorm (fp32 + optional fp16) ----
__global__ __launch_bounds__(256)
void add_ln_kernel(const float* __restrict__ resid, const float* __restrict__ y,
                   const float* __restrict__ g, const float* __restrict__ be,
                   float* __restrict__ out, __half* __restrict__ out16)
{
    const size_t base = (size_t)blockIdx.x * 1024;
    const int t = threadIdx.x;
    __shared__ float red[8];

    float v[4];
    float s = 0;
    #pragma unroll
    for (int i = 0; i < 4; i++) {
        v[i] = resid[base + t + i * 256] + y[base + t + i * 256];
        s += v[i];
    }
    #pragma unroll
    for (int o = 16; o; o >>= 1) s += __shfl_xor_sync(~0u, s, o);
    if ((t & 31) == 0) red[t >> 5] = s;
    __syncthreads();
    float tot = 0;
    #pragma unroll
    for (int i = 0; i < 8; i++) tot += red[i];
    float mean = tot * (1.0f / 1024.0f);
    __syncthreads();

    float vs = 0;
    #pragma unroll
    for (int i = 0; i < 4; i++) { float d = v[i] - mean; vs += d * d; }
    #pragma unroll
    for (int o = 16; o; o >>= 1) vs += __shfl_xor_sync(~0u, vs, o);
    if ((t & 31) == 0) red[t >> 5] = vs;
    __syncthreads();
    tot = 0;
    #pragma unroll
    for (int i = 0; i < 8; i++) tot += red[i];
    float inv = rsqrtf(tot * (1.0f / 1024.0f) + 1e-5f);

    #pragma unroll
    for (int i = 0; i < 4; i++) {
        int c = t + i * 256;
        float r = g[c] * (v[i] - mean) * inv + be[c];
        out[base + c] = r;
        if (out16) out16[base + c] = __float2half(r);
    }
}

// ================================ launch ===================================
extern "C" void kernel_launch(void* const* d_in, const int* in_sizes, int n_in,
                              void* d_out, int out_size)
{
    const float* x      = (const float*)d_in[0];
    const float* enc_x  = (const float*)d_in[1];
    const float* w_qkv  = (const float*)d_in[2];
    const float* b_qkv  = (const float*)d_in[3];
    const float* w_sa_o = (const float*)d_in[4];
    const float* b_sa_o = (const float*)d_in[5];
    const float* w_q    = (const float*)d_in[6];
    const float* b_q    = (const float*)d_in[7];
    const float* w_k    = (const float*)d_in[8];
    const float* b_k    = (const float*)d_in[9];
    const float* w_v    = (const float*)d_in[10];
    const float* b_v    = (const float*)d_in[11];
    const float* w_ca_o = (const float*)d_in[12];
    const float* b_ca_o = (const float*)d_in[13];
    const float* w1     = (const float*)d_in[14];
    const float* b1     = (const float*)d_in[15];
    const float* w2     = (const float*)d_in[16];
    const float* b2     = (const float*)d_in[17];
    const float* g1     = (const float*)d_in[18];
    const float* be1    = (const float*)d_in[19];
    const float* g2     = (const float*)d_in[20];
    const float* be2    = (const float*)d_in[21];
    const float* g3     = (const float*)d_in[22];
    const float* be3    = (const float*)d_in[23];
    float* out = (float*)d_out;

    float *p_tmp, *p_h1, *p_h2;
    cudaGetSymbolAddress((void**)&p_tmp,  g_tmp);
    cudaGetSymbolAddress((void**)&p_h1,   g_h1);
    cudaGetSymbolAddress((void**)&p_h2,   g_h2);

    __half *p_x16, *p_ex16, *p_qkv16, *p_attn16, *p_h16, *p_q16, *p_k16, *p_v16, *p_f116;
    __half *p_vts, *p_vt;
    __half *p_wqkvT, *p_wsaoT, *p_wqT, *p_wkT, *p_wvT, *p_wcaoT, *p_w1T, *p_w2T;
    cudaGetSymbolAddress((void**)&p_x16,    g_x16);
    cudaGetSymbolAddress((void**)&p_ex16,   g_ex16);
    cudaGetSymbolAddress((void**)&p_qkv16,  g_qkv16);
    cudaGetSymbolAddress((void**)&p_attn16, g_attn16);
    cudaGetSymbolAddress((void**)&p_h16,    g_h16);
    cudaGetSymbolAddress((void**)&p_q16,    g_q16);
    cudaGetSymbolAddress((void**)&p_k16,    g_k16);
    cudaGetSymbolAddress((void**)&p_v16,    g_v16);
    cudaGetSymbolAddress((void**)&p_f116,   g_f116);
    cudaGetSymbolAddress((void**)&p_vts,    g_vts);
    cudaGetSymbolAddress((void**)&p_vt,     g_vt);
    cudaGetSymbolAddress((void**)&p_wqkvT,  g_wqkvT);
    cudaGetSymbolAddress((void**)&p_wsaoT,  g_wsaoT);
    cudaGetSymbolAddress((void**)&p_wqT,    g_wqT);
    cudaGetSymbolAddress((void**)&p_wkT,    g_wkT);
    cudaGetSymbolAddress((void**)&p_wvT,    g_wvT);
    cudaGetSymbolAddress((void**)&p_wcaoT,  g_wcaoT);
    cudaGetSymbolAddress((void**)&p_w1T,    g_w1T);
    cudaGetSymbolAddress((void**)&p_w2T,    g_w2T);

    cudaFuncSetAttribute(gemm_tc,  cudaFuncAttributeMaxDynamicSharedMemorySize, GEMM_SMEM);
    cudaFuncSetAttribute(gemm3_tc, cudaFuncAttributeMaxDynamicSharedMemorySize, GEMM_SMEM);

    const dim3 blk256(256);
    const dim3 fgrd(S_ / 64, B_ * H_);

    // ---- single fused prep: all weight transposes + input converts ----
    prep_kernel<<<PREP_BLOCKS, 1024>>>(w_qkv, w_sa_o, w_q, w_k, w_v, w_ca_o, w1, w2,
                                       x, enc_x,
                                       p_wqkvT, p_wsaoT, p_wqT, p_wkT, p_wvT, p_wcaoT,
                                       p_w1T, p_w2T, p_x16, p_ex16);

    // ---- merged: self-QKV + cross-K + cross-V (all independent) ----
    gemm3_tc<<<dim3(20, MROWS / TM), 256, GEMM_SMEM>>>(
        p_x16, p_ex16, p_wqkvT, p_wkT, p_wvT,
        b_qkv, b_k, b_v, p_qkv16, p_k16, p_v16);

    // ---- V transpose for both attentions ----
    vtrans_kernel<<<8192, blk256>>>(p_qkv16, p_v16, p_vts, p_vt);

    // ---- masked self-attention ----
    flash_kernel<<<fgrd, 128>>>(p_qkv16, p_qkv16, p_vts, p_attn16,
                                3 * D_, 3 * D_, 192, 192, 64, 1);
    gemm_tc<<<dim3(D_ / TN, MROWS / TM), 256, GEMM_SMEM>>>(
        p_attn16, p_wsaoT, b_sa_o, p_tmp, (__half*)0, MROWS, D_, D_, 0);
    add_ln_kernel<<<MROWS, blk256>>>(x, p_tmp, g1, be1, p_h1, p_h16);

    // ---- cross-attention ----
    gemm_tc<<<dim3(D_ / TN, MROWS / TM), 256, GEMM_SMEM>>>(
        p_h16, p_wqT, b_q, (float*)0, p_q16, MROWS, D_, D_, 0);
    flash_kernel<<<fgrd, 128>>>(p_q16, p_k16, p_vt, p_attn16,
                                D_, D_, 64, 64, 0, 0);
    gemm_tc<<<dim3(D_ / TN, MROWS / TM), 256, GEMM_SMEM>>>(
        p_attn16, p_wcaoT, b_ca_o, p_tmp, (__half*)0, MROWS, D_, D_, 0);
    add_ln_kernel<<<MROWS, blk256>>>(p_h1, p_tmp, g2, be2, p_h2, p_h16);

    // ---- FFN ----
    gemm_tc<<<dim3(DFF_ / TN, MROWS / TM), 256, GEMM_SMEM>>>(
        p_h16, p_w1T, b1, (float*)0, p_f116, MROWS, DFF_, D_, 1);
    gemm_tc<<<dim3(D_ / TN, MROWS / TM), 256, GEMM_SMEM>>>(
        p_f116, p_w2T, b2, p_tmp, (__half*)0, MROWS, D_, DFF_, 0);
    add_ln_kernel<<<MROWS, blk256>>>(p_h2, p_tmp, g3, be3, out, (__half*)0);
}

// round 16
// speedup vs baseline: 1.0084x; 1.0084x over previous
#include <cuda_runtime.h>
#include <cuda_fp16.h>
#include <math.h>
#include <stdint.h>

// Problem constants
#define B_   4
#define S_   1024
#define E_   1024
#define D_   1024
#define H_   16
#define DH_  64
#define DFF_ 4096
#define MROWS (B_*S_)   // 4096

__device__ __forceinline__ uint32_t smem_u32(const void* p) {
    uint32_t a;
    asm("{ .reg .u64 t; cvta.to.shared.u64 t, %1; cvt.u32.u64 %0, t; }"
        : "=r"(a) : "l"(p));
    return a;
}
__device__ __forceinline__ float ex2f(float x) {
    float y;
    asm("ex2.approx.ftz.f32 %0, %1;" : "=f"(y) : "f"(x));
    return y;
}

// ============================= scratch =====================================
__device__ float  g_tmp   [(size_t)MROWS * D_];
__device__ float  g_h1    [(size_t)MROWS * D_];
__device__ float  g_h2    [(size_t)MROWS * D_];

__device__ __half g_x16   [(size_t)MROWS * D_];
__device__ __half g_ex16  [(size_t)B_ * E_ * D_];
__device__ __half g_qkv16 [(size_t)MROWS * 3 * D_];
__device__ __half g_attn16[(size_t)MROWS * D_];
__device__ __half g_h16   [(size_t)MROWS * D_];
__device__ __half g_q16   [(size_t)MROWS * D_];
__device__ __half g_k16   [(size_t)B_ * E_ * D_];
__device__ __half g_v16   [(size_t)B_ * E_ * D_];
__device__ __half g_f116  [(size_t)MROWS * DFF_];
__device__ __half g_wqkvT [(size_t)3 * D_ * D_];
__device__ __half g_wsaoT [(size_t)D_ * D_];
__device__ __half g_wqT   [(size_t)D_ * D_];
__device__ __half g_wkT   [(size_t)D_ * D_];
__device__ __half g_wvT   [(size_t)D_ * D_];
__device__ __half g_wcaoT [(size_t)D_ * D_];
__device__ __half g_w1T   [(size_t)D_ * DFF_];
__device__ __half g_w2T   [(size_t)DFF_ * D_];

// ==================== fused prep: all transposes + converts ================
#define PREP_BLOCKS 18432

__global__ __launch_bounds__(1024)
void prep_kernel(const float* __restrict__ w_qkv, const float* __restrict__ w_sa_o,
                 const float* __restrict__ w_q,  const float* __restrict__ w_k,
                 const float* __restrict__ w_v,  const float* __restrict__ w_ca_o,
                 const float* __restrict__ w1,   const float* __restrict__ w2,
                 const float* __restrict__ x,    const float* __restrict__ enc_x,
                 __half* __restrict__ wqkvT, __half* __restrict__ wsaoT,
                 __half* __restrict__ wqT,   __half* __restrict__ wkT,
                 __half* __restrict__ wvT,   __half* __restrict__ wcaoT,
                 __half* __restrict__ w1T,   __half* __restrict__ w2T,
                 __half* __restrict__ x16,   __half* __restrict__ ex16)
{
    const int bid = blockIdx.x;
    const int tx = threadIdx.x & 31;
    const int ty = threadIdx.x >> 5;

    const float* src; __half* dst; int K, N, tile, nx;
    if (bid < 16384) {
        if (bid < 3072)       { src = w_qkv;  dst = wqkvT; K = D_;   N = 3 * D_; tile = bid;         nx = 96;  }
        else if (bid < 4096)  { src = w_sa_o; dst = wsaoT; K = D_;   N = D_;     tile = bid - 3072;  nx = 32;  }
        else if (bid < 5120)  { src = w_q;    dst = wqT;   K = D_;   N = D_;     tile = bid - 4096;  nx = 32;  }
        else if (bid < 6144)  { src = w_k;    dst = wkT;   K = D_;   N = D_;     tile = bid - 5120;  nx = 32;  }
        else if (bid < 7168)  { src = w_v;    dst = wvT;   K = D_;   N = D_;     tile = bid - 6144;  nx = 32;  }
        else if (bid < 8192)  { src = w_ca_o; dst = wcaoT; K = D_;   N = D_;     tile = bid - 7168;  nx = 32;  }
        else if (bid < 12288) { src = w1;     dst = w1T;   K = D_;   N = DFF_;   tile = bid - 8192;  nx = 128; }
        else                  { src = w2;     dst = w2T;   K = DFF_; N = D_;     tile = bid - 12288; nx = 32;  }

        __shared__ float t[32][33];
        const int bx = tile % nx, by = tile / nx;
        int k = by * 32 + ty;
        int n = bx * 32 + tx;
        t[ty][tx] = src[(size_t)k * N + n];
        __syncthreads();
        int nn = bx * 32 + ty;
        int kk = by * 32 + tx;
        dst[(size_t)nn * K + kk] = __float2half(t[tx][ty]);
    } else {
        const int cb = bid - 16384;
        const float4* in;
        __half2* out;
        int base;
        if (cb < 1024) { in = (const float4*)x;     out = (__half2*)x16;  base = cb; }
        else           { in = (const float4*)enc_x; out = (__half2*)ex16; base = cb - 1024; }
        int i = base * 1024 + (int)threadIdx.x;
        float4 v = in[i];
        out[2 * i]     = __floats2half2_rn(v.x, v.y);
        out[2 * i + 1] = __floats2half2_rn(v.z, v.w);
    }
}

// ========================= mma primitives ==================================
__device__ __forceinline__ void ldmx4(uint32_t* r, uint32_t addr) {
    asm volatile("ldmatrix.sync.aligned.m8n8.x4.shared.b16 {%0,%1,%2,%3}, [%4];"
                 : "=r"(r[0]), "=r"(r[1]), "=r"(r[2]), "=r"(r[3]) : "r"(addr));
}
__device__ __forceinline__ void ldmx4t(uint32_t* r, uint32_t addr) {
    asm volatile("ldmatrix.sync.aligned.m8n8.x4.trans.shared.b16 {%0,%1,%2,%3}, [%4];"
                 : "=r"(r[0]), "=r"(r[1]), "=r"(r[2]), "=r"(r[3]) : "r"(addr));
}
__device__ __forceinline__ void mma16816(float* c, const uint32_t* a, const uint32_t* b) {
    asm volatile("mma.sync.aligned.m16n8k16.row.col.f32.f16.f16.f32 "
                 "{%0,%1,%2,%3}, {%4,%5,%6,%7}, {%8,%9}, {%0,%1,%2,%3};"
                 : "+f"(c[0]), "+f"(c[1]), "+f"(c[2]), "+f"(c[3])
                 : "r"(a[0]), "r"(a[1]), "r"(a[2]), "r"(a[3]), "r"(b[0]), "r"(b[1]));
}
#define CP_ASYNC16(smem, gmem) \
    asm volatile("cp.async.cg.shared.global [%0], [%1], 16;" \
                 :: "r"(smem), "l"(gmem) : "memory")
#define CP_COMMIT() asm volatile("cp.async.commit_group;" ::: "memory")
#define CP_WAIT0()  asm volatile("cp.async.wait_group 0;" ::: "memory")
#define CP_WAIT1()  asm volatile("cp.async.wait_group 1;" ::: "memory")

// ===================== mma.sync fp16 GEMM body =============================
// CTA tile 128x256x32, 8 warps (2m x 4n), warp tile 64x64.
// 3-stage cp.async ring + register fragment double-buffering.
#define TM 128
#define TN 256
#define KC 32
#define PAD 40
#define A_STAGE (TM * PAD * 2)               // 10240 B
#define B_STAGE (TN * PAD * 2)               // 20480 B
#define GEMM_SMEM (3 * (A_STAGE + B_STAGE))  // 92160 B

__device__ __forceinline__ void gemm_body(
    const __half* __restrict__ A, const __half* __restrict__ Bt,
    const float* __restrict__ bias, float* __restrict__ outf,
    __half* __restrict__ outh, int N, int K, int act,
    int m0, int n0, uint32_t sbase)
{
    #define SA_ADDR(st, r, c) (sbase + (uint32_t)(st) * A_STAGE + (uint32_t)((r) * PAD + (c)) * 2)
    #define SB_ADDR(st, r, c) (sbase + 3u * A_STAGE + (uint32_t)(st) * B_STAGE + (uint32_t)((r) * PAD + (c)) * 2)

    const int tid  = threadIdx.x;
    const int lane = tid & 31;
    const int wid  = tid >> 5;
    const int wm   = wid & 1;
    const int wn   = wid >> 1;

    float acc[4][8][4];
    #pragma unroll
    for (int i = 0; i < 4; i++)
        #pragma unroll
        for (int j = 0; j < 8; j++)
            #pragma unroll
            for (int q = 0; q < 4; q++) acc[i][j][q] = 0.f;

    const int r0c = tid >> 1;
    const int j0c = (tid & 1) * 2;
    const int nch = K / KC;

    #define ISSUE_CHUNK(cc_, stg_) do {                                              \
        const __half* Ag_ = A  + (size_t)m0 * K + (cc_) * KC;                        \
        const __half* Bg_ = Bt + (size_t)n0 * K + (cc_) * KC;                        \
        _Pragma("unroll")                                                            \
        for (int j = 0; j < 2; j++)                                                  \
            CP_ASYNC16(SA_ADDR(stg_, r0c, (j0c + j) * 8), Ag_ + (size_t)r0c * K + (j0c + j) * 8); \
        _Pragma("unroll")                                                            \
        for (int h = 0; h < 2; h++) {                                                \
            int rb_ = r0c + h * 128;                                                 \
            _Pragma("unroll")                                                        \
            for (int j = 0; j < 2; j++)                                              \
                CP_ASYNC16(SB_ADDR(stg_, rb_, (j0c + j) * 8), Bg_ + (size_t)rb_ * K + (j0c + j) * 8); \
        }                                                                            \
    } while (0)

    #define LDFRAGS(stg_, ks_, AF, BF) do {                                          \
        _Pragma("unroll")                                                            \
        for (int mi = 0; mi < 4; mi++) {                                             \
            int r_  = wm * 64 + mi * 16 + (lane & 15);                               \
            int cc_ = (ks_) * 16 + ((lane >> 4) << 3);                               \
            ldmx4((AF)[mi], SA_ADDR(stg_, r_, cc_));                                 \
        }                                                                            \
        _Pragma("unroll")                                                            \
        for (int nj = 0; nj < 4; nj++) {                                             \
            int r_  = wn * 64 + nj * 16 + ((lane & 7) | ((lane & 16) >> 1));         \
            int cc_ = (ks_) * 16 + (((lane >> 3) & 1) << 3);                         \
            ldmx4((BF)[nj], SB_ADDR(stg_, r_, cc_));                                 \
        }                                                                            \
    } while (0)

    #define MMASET(AF, BF) do {                                                      \
        _Pragma("unroll")                                                            \
        for (int mi = 0; mi < 4; mi++)                                               \
            _Pragma("unroll")                                                        \
            for (int nj = 0; nj < 8; nj++)                                           \
                mma16816(acc[mi][nj], (AF)[mi], &(BF)[nj >> 1][(nj & 1) * 2]);       \
    } while (0)

    ISSUE_CHUNK(0, 0); CP_COMMIT();
    ISSUE_CHUNK(1, 1); CP_COMMIT();
    CP_WAIT1();
    __syncthreads();

    uint32_t afr0[4][4], bfr0[4][4], afr1[4][4], bfr1[4][4];
    LDFRAGS(0, 0, afr0, bfr0);

    int st = 0, stw = 2;
    for (int c = 0; c < nch; c++) {
        if (c + 2 < nch) ISSUE_CHUNK(c + 2, stw);
        CP_COMMIT();

        LDFRAGS(st, 1, afr1, bfr1);
        MMASET(afr0, bfr0);

        if (c + 1 < nch) {
            CP_WAIT1();
            __syncthreads();
            const int nst = (st == 2) ? 0 : st + 1;
            LDFRAGS(nst, 0, afr0, bfr0);
        }
        MMASET(afr1, bfr1);

        st  = (st  == 2) ? 0 : st  + 1;
        stw = (stw == 2) ? 0 : stw + 1;
    }

    #pragma unroll
    for (int mi = 0; mi < 4; mi++) {
        #pragma unroll
        for (int rr = 0; rr < 2; rr++) {
            const int row = m0 + wm * 64 + mi * 16 + rr * 8 + (lane >> 2);
            #pragma unroll
            for (int nj = 0; nj < 8; nj++) {
                const int col = n0 + wn * 64 + nj * 8 + (lane & 3) * 2;
                float v0 = acc[mi][nj][rr * 2 + 0] + bias[col];
                float v1 = acc[mi][nj][rr * 2 + 1] + bias[col + 1];
                if (act) {
                    v0 = 0.5f * v0 * (1.0f + erff(v0 * 0.70710678118654752f));
                    v1 = 0.5f * v1 * (1.0f + erff(v1 * 0.70710678118654752f));
                }
                if (outf)
                    *(float2*)(outf + (size_t)row * N + col) = make_float2(v0, v1);
                if (outh)
                    *(__half2*)(outh + (size_t)row * N + col) = __floats2half2_rn(v0, v1);
            }
        }
    }
    #undef SA_ADDR
    #undef SB_ADDR
    #undef ISSUE_CHUNK
    #undef LDFRAGS
    #undef MMASET
}

__global__ void __launch_bounds__(256)
gemm_tc(const __half* __restrict__ A, const __half* __restrict__ Bt,
        const float* __restrict__ bias, float* __restrict__ outf,
        __half* __restrict__ outh, int M, int N, int K, int act)
{
    extern __shared__ char dynsm[];
    gemm_body(A, Bt, bias, outf, outh, N, K, act,
              blockIdx.y * TM, blockIdx.x * TN, smem_u32(dynsm));
}

__global__ void __launch_bounds__(256)
gemm3_tc(const __half* __restrict__ A0, const __half* __restrict__ A12,
         const __half* __restrict__ W0, const __half* __restrict__ W1,
         const __half* __restrict__ W2,
         const float* __restrict__ b0, const float* __restrict__ b1,
         const float* __restrict__ b2,
         __half* __restrict__ o0, __half* __restrict__ o1, __half* __restrict__ o2)
{
    extern __shared__ char dynsm[];
    const int bx = blockIdx.x;
    const __half *A, *W; const float* bias; __half* outh; int N, n0;
    if (bx < 12)      { A = A0;  W = W0; bias = b0; outh = o0; N = 3 * D_; n0 = bx * TN; }
    else if (bx < 16) { A = A12; W = W1; bias = b1; outh = o1; N = D_;     n0 = (bx - 12) * TN; }
    else              { A = A12; W = W2; bias = b2; outh = o2; N = D_;     n0 = (bx - 16) * TN; }
    gemm_body(A, W, bias, (float*)0, outh, N, D_, 0,
              blockIdx.y * TM, n0, smem_u32(dynsm));
}

// ================= fused flash attention (fp16 mma) ========================
// 128 Q rows per CTA, 8 warps (16 rows each), 256 threads. K tiles of 64.
// Base-2 softmax: Q pre-scaled by 0.125*log2(e); exp == single MUFU ex2.
__global__ void __launch_bounds__(256, 2)
flash_kernel(const __half* __restrict__ Qp, const __half* __restrict__ Kp,
             const __half* __restrict__ Vp, __half* __restrict__ Op,
             int qrs, int krs, int qhs, int khs, int kadd, int vadd, int causal)
{
    __shared__ __align__(16) __half sQ[128][72];
    __shared__ __align__(16) __half sK[2][64][72];
    __shared__ __align__(16) __half sV[2][64][72];

    const int tid  = threadIdx.x;
    const int lane = tid & 31;
    const int warp = tid >> 5;           // 0..7
    const int bh = blockIdx.y;
    const int b  = bh >> 4;
    const int h  = bh & 15;
    const int q0 = blockIdx.x * 128;

    const __half* Qb = Qp + (size_t)(b * S_ + q0) * qrs + h * qhs;
    const __half* Kb = Kp + (size_t)(b * S_) * krs + h * khs + kadd;
    const __half* Vb = Vp + (size_t)(b * S_) * krs + h * khs + vadd;

    // Q load: 128 rows x 8 chunks = 1024 chunks; 4 per thread. Scale by 1/8*log2e.
    const __half2 scq = __float2half2_rn(0.125f * 1.44269504088896f);
    #pragma unroll
    for (int i = 0; i < 4; i++) {
        int ch = tid + i * 256;
        int r = ch >> 3, j = ch & 7;
        uint4 u = *(const uint4*)(Qb + (size_t)r * qrs + j * 8);
        __half2* hp = (__half2*)&u;
        #pragma unroll
        for (int q = 0; q < 4; q++) hp[q] = __hmul2(hp[q], scq);
        *(uint4*)&sQ[r][j * 8] = u;
    }
    // first K/V tile: 64 rows x 8 chunks = 512 chunks; 2 per thread
    #pragma unroll
    for (int i = 0; i < 2; i++) {
        int ch = tid + i * 256;
        int r = ch >> 3, j = ch & 7;
        CP_ASYNC16(smem_u32(&sK[0][r][j * 8]), Kb + (size_t)r * krs + j * 8);
        CP_ASYNC16(smem_u32(&sV[0][r][j * 8]), Vb + (size_t)r * krs + j * 8);
    }
    CP_COMMIT();

    uint32_t qf[4][4];
    float m0 = -1e30f, m1 = -1e30f, l0 = 0.f, l1 = 0.f;
    float o[8][4];
    #pragma unroll
    for (int nj = 0; nj < 8; nj++)
        #pragma unroll
        for (int q = 0; q < 4; q++) o[nj][q] = 0.f;

    const int nkt = causal ? (2 * (blockIdx.x + 1)) : (S_ / 64);

    for (int kt = 0; kt < nkt; kt++) {
        CP_WAIT0();
        __syncthreads();

        if (kt == 0) {
            #pragma unroll
            for (int ks = 0; ks < 4; ks++) {
                int r  = warp * 16 + (lane & 15);
                int cc = ks * 16 + ((lane >> 4) << 3);
                ldmx4(qf[ks], smem_u32(&sQ[r][cc]));
            }
        }
        if (kt + 1 < nkt) {
            const int nb = (kt + 1) & 1;
            #pragma unroll
            for (int i = 0; i < 2; i++) {
                int ch = tid + i * 256;
                int r = ch >> 3, j = ch & 7;
                CP_ASYNC16(smem_u32(&sK[nb][r][j * 8]), Kb + (size_t)((kt + 1) * 64 + r) * krs + j * 8);
                CP_ASYNC16(smem_u32(&sV[nb][r][j * 8]), Vb + (size_t)((kt + 1) * 64 + r) * krs + j * 8);
            }
            CP_COMMIT();
        }
        const int cb = kt & 1;

        float s[8][4];
        #pragma unroll
        for (int nj = 0; nj < 8; nj++)
            #pragma unroll
            for (int q = 0; q < 4; q++) s[nj][q] = 0.f;

        #pragma unroll
        for (int ks = 0; ks < 4; ks++) {
            #pragma unroll
            for (int nj2 = 0; nj2 < 4; nj2++) {
                uint32_t bf[4];
                int r  = nj2 * 16 + ((lane & 7) | ((lane & 16) >> 1));
                int cc = ks * 16 + (((lane >> 3) & 1) << 3);
                ldmx4(bf, smem_u32(&sK[cb][r][cc]));
                mma16816(s[2 * nj2],     qf[ks], &bf[0]);
                mma16816(s[2 * nj2 + 1], qf[ks], &bf[2]);
            }
        }

        // causal mask (global indices); only for warps intersecting the diagonal
        if (causal && (kt * 64 + 63 > q0 + warp * 16)) {
            int rl = q0 + warp * 16 + (lane >> 2);
            int c0 = kt * 64 + (lane & 3) * 2;
            #pragma unroll
            for (int nj = 0; nj < 8; nj++) {
                int kg = c0 + nj * 8;
                if (kg     > rl)     s[nj][0] = -1e30f;
                if (kg + 1 > rl)     s[nj][1] = -1e30f;
                if (kg     > rl + 8) s[nj][2] = -1e30f;
                if (kg + 1 > rl + 8) s[nj][3] = -1e30f;
            }
        }

        float mx0 = -1e30f, mx1 = -1e30f;
        #pragma unroll
        for (int nj = 0; nj < 8; nj++) {
            mx0 = fmaxf(mx0, fmaxf(s[nj][0], s[nj][1]));
            mx1 = fmaxf(mx1, fmaxf(s[nj][2], s[nj][3]));
        }
        mx0 = fmaxf(mx0, __shfl_xor_sync(~0u, mx0, 1));
        mx0 = fmaxf(mx0, __shfl_xor_sync(~0u, mx0, 2));
        mx1 = fmaxf(mx1, __shfl_xor_sync(~0u, mx1, 1));
        mx1 = fmaxf(mx1, __shfl_xor_sync(~0u, mx1, 2));

        float nm0 = fmaxf(m0, mx0), nm1 = fmaxf(m1, mx1);
        float sc0 = ex2f(m0 - nm0), sc1 = ex2f(m1 - nm1);
        m0 = nm0; m1 = nm1;
        l0 *= sc0; l1 *= sc1;
        #pragma unroll
        for (int nj = 0; nj < 8; nj++) {
            o[nj][0] *= sc0; o[nj][1] *= sc0;
            o[nj][2] *= sc1; o[nj][3] *= sc1;
        }

        uint32_t pk[8][2];
        float rs0 = 0.f, rs1 = 0.f;
        #pragma unroll
        for (int nj = 0; nj < 8; nj++) {
            float p0 = ex2f(s[nj][0] - m0), p1 = ex2f(s[nj][1] - m0);
            float p2 = ex2f(s[nj][2] - m1), p3 = ex2f(s[nj][3] - m1);
            rs0 += p0 + p1; rs1 += p2 + p3;
            __half2 hA = __floats2half2_rn(p0, p1);
            __half2 hB = __floats2half2_rn(p2, p3);
            pk[nj][0] = *(uint32_t*)&hA;
            pk[nj][1] = *(uint32_t*)&hB;
        }
        l0 += rs0; l1 += rs1;

        #pragma unroll
        for (int t = 0; t < 4; t++) {
            uint32_t a[4] = { pk[2 * t][0], pk[2 * t][1], pk[2 * t + 1][0], pk[2 * t + 1][1] };
            #pragma unroll
            for (int nj2 = 0; nj2 < 4; nj2++) {
                uint32_t bf[4];
                int r  = t * 16 + (lane & 15);
                int cc = nj2 * 16 + ((lane >> 4) << 3);
                ldmx4t(bf, smem_u32(&sV[cb][r][cc]));
                mma16816(o[2 * nj2],     a, &bf[0]);
                mma16816(o[2 * nj2 + 1], a, &bf[2]);
            }
        }
    }

    l0 += __shfl_xor_sync(~0u, l0, 1);
    l0 += __shfl_xor_sync(~0u, l0, 2);
    l1 += __shfl_xor_sync(~0u, l1, 1);
    l1 += __shfl_xor_sync(~0u, l1, 2);
    float inv0 = 1.f / l0, inv1 = 1.f / l1;

    const int row0 = q0 + warp * 16 + (lane >> 2);
    #pragma unroll
    for (int nj = 0; nj < 8; nj++) {
        int col = h * 64 + nj * 8 + (lane & 3) * 2;
        *(__half2*)(Op + (size_t)(b * S_ + row0) * D_ + col) =
            __floats2half2_rn(o[nj][0] * inv0, o[nj][1] * inv0);
        *(__half2*)(Op + (size_t)(b * S_ + row0 + 8) * D_ + col) =
            __floats2half2_rn(o[nj][2] * inv1, o[nj][3] * inv1);
    }
}

// ---------------- fused residual-add + LayerNorm (fp32 + optional fp16) ----
__global__ __launch_bounds__(256)
void add_ln_kernel(const float* __restrict__ resid, const float* __restrict__ y,
                   const float* __restrict__ g, const float* __restrict__ be,
                   float* __restrict__ out, __half* __restrict__ out16)
{
    const size_t base = (size_t)blockIdx.x * 1024;
    const int t = threadIdx.x;
    __shared__ float red[8];

    float v[4];
    float s = 0;
    #pragma unroll
    for (int i = 0; i < 4; i++) {
        v[i] = resid[base + t + i * 256] + y[base + t + i * 256];
        s += v[i];
    }
    #pragma unroll
    for (int o = 16; o; o >>= 1) s += __shfl_xor_sync(~0u, s, o);
    if ((t & 31) == 0) red[t >> 5] = s;
    __syncthreads();
    float tot = 0;
    #pragma unroll
    for (int i = 0; i < 8; i++) tot += red[i];
    float mean = tot * (1.0f / 1024.0f);
    __syncthreads();

    float vs = 0;
    #pragma unroll
    for (int i = 0; i < 4; i++) { float d = v[i] - mean; vs += d * d; }
    #pragma unroll
    for (int o = 16; o; o >>= 1) vs += __shfl_xor_sync(~0u, vs, o);
    if ((t & 31) == 0) red[t >> 5] = vs;
    __syncthreads();
    tot = 0;
    #pragma unroll
    for (int i = 0; i < 8; i++) tot += red[i];
    float inv = rsqrtf(tot * (1.0f / 1024.0f) + 1e-5f);

    #pragma unroll
    for (int i = 0; i < 4; i++) {
        int c = t + i * 256;
        float r = g[c] * (v[i] - mean) * inv + be[c];
        out[base + c] = r;
        if (out16) out16[base + c] = __float2half(r);
    }
}

// ================================ launch ===================================
extern "C" void kernel_launch(void* const* d_in, const int* in_sizes, int n_in,
                              void* d_out, int out_size)
{
    const float* x      = (const float*)d_in[0];
    const float* enc_x  = (const float*)d_in[1];
    const float* w_qkv  = (const float*)d_in[2];
    const float* b_qkv  = (const float*)d_in[3];
    const float* w_sa_o = (const float*)d_in[4];
    const float* b_sa_o = (const float*)d_in[5];
    const float* w_q    = (const float*)d_in[6];
    const float* b_q    = (const float*)d_in[7];
    const float* w_k    = (const float*)d_in[8];
    const float* b_k    = (const float*)d_in[9];
    const float* w_v    = (const float*)d_in[10];
    const float* b_v    = (const float*)d_in[11];
    const float* w_ca_o = (const float*)d_in[12];
    const float* b_ca_o = (const float*)d_in[13];
    const float* w1     = (const float*)d_in[14];
    const float* b1     = (const float*)d_in[15];
    const float* w2     = (const float*)d_in[16];
    const float* b2     = (const float*)d_in[17];
    const float* g1     = (const float*)d_in[18];
    const float* be1    = (const float*)d_in[19];
    const float* g2     = (const float*)d_in[20];
    const float* be2    = (const float*)d_in[21];
    const float* g3     = (const float*)d_in[22];
    const float* be3    = (const float*)d_in[23];
    float* out = (float*)d_out;

    float *p_tmp, *p_h1, *p_h2;
    cudaGetSymbolAddress((void**)&p_tmp,  g_tmp);
    cudaGetSymbolAddress((void**)&p_h1,   g_h1);
    cudaGetSymbolAddress((void**)&p_h2,   g_h2);

    __half *p_x16, *p_ex16, *p_qkv16, *p_attn16, *p_h16, *p_q16, *p_k16, *p_v16, *p_f116;
    __half *p_wqkvT, *p_wsaoT, *p_wqT, *p_wkT, *p_wvT, *p_wcaoT, *p_w1T, *p_w2T;
    cudaGetSymbolAddress((void**)&p_x16,    g_x16);
    cudaGetSymbolAddress((void**)&p_ex16,   g_ex16);
    cudaGetSymbolAddress((void**)&p_qkv16,  g_qkv16);
    cudaGetSymbolAddress((void**)&p_attn16, g_attn16);
    cudaGetSymbolAddress((void**)&p_h16,    g_h16);
    cudaGetSymbolAddress((void**)&p_q16,    g_q16);
    cudaGetSymbolAddress((void**)&p_k16,    g_k16);
    cudaGetSymbolAddress((void**)&p_v16,    g_v16);
    cudaGetSymbolAddress((void**)&p_f116,   g_f116);
    cudaGetSymbolAddress((void**)&p_wqkvT,  g_wqkvT);
    cudaGetSymbolAddress((void**)&p_wsaoT,  g_wsaoT);
    cudaGetSymbolAddress((void**)&p_wqT,    g_wqT);
    cudaGetSymbolAddress((void**)&p_wkT,    g_wkT);
    cudaGetSymbolAddress((void**)&p_wvT,    g_wvT);
    cudaGetSymbolAddress((void**)&p_wcaoT,  g_wcaoT);
    cudaGetSymbolAddress((void**)&p_w1T,    g_w1T);
    cudaGetSymbolAddress((void**)&p_w2T,    g_w2T);

    cudaFuncSetAttribute(gemm_tc,  cudaFuncAttributeMaxDynamicSharedMemorySize, GEMM_SMEM);
    cudaFuncSetAttribute(gemm3_tc, cudaFuncAttributeMaxDynamicSharedMemorySize, GEMM_SMEM);

    const dim3 blk256(256);
    const dim3 fgrd(S_ / 128, B_ * H_);

    // ---- single fused prep: all weight transposes + input converts ----
    prep_kernel<<<PREP_BLOCKS, 1024>>>(w_qkv, w_sa_o, w_q, w_k, w_v, w_ca_o, w1, w2,
                                       x, enc_x,
                                       p_wqkvT, p_wsaoT, p_wqT, p_wkT, p_wvT, p_wcaoT,
                                       p_w1T, p_w2T, p_x16, p_ex16);

    // ---- merged: self-QKV + cross-K + cross-V (all independent) ----
    gemm3_tc<<<dim3(20, MROWS / TM), 256, GEMM_SMEM>>>(
        p_x16, p_ex16, p_wqkvT, p_wkT, p_wvT,
        b_qkv, b_k, b_v, p_qkv16, p_k16, p_v16);

    // ---- masked self-attention ----
    flash_kernel<<<fgrd, 256>>>(p_qkv16, p_qkv16, p_qkv16, p_attn16,
                                3 * D_, 3 * D_, 192, 192, 64, 128, 1);
    gemm_tc<<<dim3(D_ / TN, MROWS / TM), 256, GEMM_SMEM>>>(
        p_attn16, p_wsaoT, b_sa_o, p_tmp, (__half*)0, MROWS, D_, D_, 0);
    add_ln_kernel<<<MROWS, blk256>>>(x, p_tmp, g1, be1, p_h1, p_h16);

    // ---- cross-attention ----
    gemm_tc<<<dim3(D_ / TN, MROWS / TM), 256, GEMM_SMEM>>>(
        p_h16, p_wqT, b_q, (float*)0, p_q16, MROWS, D_, D_, 0);
    flash_kernel<<<fgrd, 256>>>(p_q16, p_k16, p_v16, p_attn16,
                                D_, D_, 64, 64, 0, 0, 0);
    gemm_tc<<<dim3(D_ / TN, MROWS / TM), 256, GEMM_SMEM>>>(
        p_attn16, p_wcaoT, b_ca_o, p_tmp, (__half*)0, MROWS, D_, D_, 0);
    add_ln_kernel<<<MROWS, blk256>>>(p_h1, p_tmp, g2, be2, p_h2, p_h16);

    // ---- FFN ----
    gemm_tc<<<dim3(DFF_ / TN, MROWS / TM), 256, GEMM_SMEM>>>(
        p_h16, p_w1T, b1, (float*)0, p_f116, MROWS, DFF_, D_, 1);
    gemm_tc<<<dim3(D_ / TN, MROWS / TM), 256, GEMM_SMEM>>>(
        p_f116, p_w2T, b2, p_tmp, (__half*)0, MROWS, D_, DFF_, 0);
    add_ln_kernel<<<MROWS, blk256>>>(p_h2, p_tmp, g3, be3, out, (__half*)0);
}

// round 17
// speedup vs baseline: 1.0955x; 1.0864x over previous
#include <cuda_runtime.h>
#include <cuda_fp16.h>
#include <math.h>
#include <stdint.h>

// Problem constants
#define B_   4
#define S_   1024
#define E_   1024
#define D_   1024
#define H_   16
#define DH_  64
#define DFF_ 4096
#define MROWS (B_*S_)   // 4096

__device__ __forceinline__ uint32_t smem_u32(const void* p) {
    uint32_t a;
    asm("{ .reg .u64 t; cvta.to.shared.u64 t, %1; cvt.u32.u64 %0, t; }"
        : "=r"(a) : "l"(p));
    return a;
}
__device__ __forceinline__ float ex2f(float x) {
    float y;
    asm("ex2.approx.ftz.f32 %0, %1;" : "=f"(y) : "f"(x));
    return y;
}

// ============================= scratch =====================================
__device__ float  g_h1    [(size_t)MROWS * D_];
__device__ float  g_h2    [(size_t)MROWS * D_];

__device__ __half g_y16   [(size_t)MROWS * D_];
__device__ __half g_x16   [(size_t)MROWS * D_];
__device__ __half g_ex16  [(size_t)B_ * E_ * D_];
__device__ __half g_qkv16 [(size_t)MROWS * 3 * D_];
__device__ __half g_attn16[(size_t)MROWS * D_];
__device__ __half g_h16   [(size_t)MROWS * D_];
__device__ __half g_q16   [(size_t)MROWS * D_];
__device__ __half g_k16   [(size_t)B_ * E_ * D_];
__device__ __half g_v16   [(size_t)B_ * E_ * D_];
__device__ __half g_f116  [(size_t)MROWS * DFF_];
__device__ __half g_wqkvT [(size_t)3 * D_ * D_];
__device__ __half g_wsaoT [(size_t)D_ * D_];
__device__ __half g_wqT   [(size_t)D_ * D_];
__device__ __half g_wkT   [(size_t)D_ * D_];
__device__ __half g_wvT   [(size_t)D_ * D_];
__device__ __half g_wcaoT [(size_t)D_ * D_];
__device__ __half g_w1T   [(size_t)D_ * DFF_];
__device__ __half g_w2T   [(size_t)DFF_ * D_];

// ==================== fused prep: all transposes + converts ================
#define PREP_BLOCKS 18432

__global__ __launch_bounds__(1024)
void prep_kernel(const float* __restrict__ w_qkv, const float* __restrict__ w_sa_o,
                 const float* __restrict__ w_q,  const float* __restrict__ w_k,
                 const float* __restrict__ w_v,  const float* __restrict__ w_ca_o,
                 const float* __restrict__ w1,   const float* __restrict__ w2,
                 const float* __restrict__ x,    const float* __restrict__ enc_x,
                 __half* __restrict__ wqkvT, __half* __restrict__ wsaoT,
                 __half* __restrict__ wqT,   __half* __restrict__ wkT,
                 __half* __restrict__ wvT,   __half* __restrict__ wcaoT,
                 __half* __restrict__ w1T,   __half* __restrict__ w2T,
                 __half* __restrict__ x16,   __half* __restrict__ ex16)
{
    const int bid = blockIdx.x;
    const int tx = threadIdx.x & 31;
    const int ty = threadIdx.x >> 5;

    const float* src; __half* dst; int K, N, tile, nx;
    if (bid < 16384) {
        if (bid < 3072)       { src = w_qkv;  dst = wqkvT; K = D_;   N = 3 * D_; tile = bid;         nx = 96;  }
        else if (bid < 4096)  { src = w_sa_o; dst = wsaoT; K = D_;   N = D_;     tile = bid - 3072;  nx = 32;  }
        else if (bid < 5120)  { src = w_q;    dst = wqT;   K = D_;   N = D_;     tile = bid - 4096;  nx = 32;  }
        else if (bid < 6144)  { src = w_k;    dst = wkT;   K = D_;   N = D_;     tile = bid - 5120;  nx = 32;  }
        else if (bid < 7168)  { src = w_v;    dst = wvT;   K = D_;   N = D_;     tile = bid - 6144;  nx = 32;  }
        else if (bid < 8192)  { src = w_ca_o; dst = wcaoT; K = D_;   N = D_;     tile = bid - 7168;  nx = 32;  }
        else if (bid < 12288) { src = w1;     dst = w1T;   K = D_;   N = DFF_;   tile = bid - 8192;  nx = 128; }
        else                  { src = w2;     dst = w2T;   K = DFF_; N = D_;     tile = bid - 12288; nx = 32;  }

        __shared__ float t[32][33];
        const int bx = tile % nx, by = tile / nx;
        int k = by * 32 + ty;
        int n = bx * 32 + tx;
        t[ty][tx] = src[(size_t)k * N + n];
        __syncthreads();
        int nn = bx * 32 + ty;
        int kk = by * 32 + tx;
        dst[(size_t)nn * K + kk] = __float2half(t[tx][ty]);
    } else {
        const int cb = bid - 16384;
        const float4* in;
        __half2* out;
        int base;
        if (cb < 1024) { in = (const float4*)x;     out = (__half2*)x16;  base = cb; }
        else           { in = (const float4*)enc_x; out = (__half2*)ex16; base = cb - 1024; }
        int i = base * 1024 + (int)threadIdx.x;
        float4 v = in[i];
        out[2 * i]     = __floats2half2_rn(v.x, v.y);
        out[2 * i + 1] = __floats2half2_rn(v.z, v.w);
    }
}

// ========================= mma primitives ==================================
__device__ __forceinline__ void ldmx4(uint32_t* r, uint32_t addr) {
    asm volatile("ldmatrix.sync.aligned.m8n8.x4.shared.b16 {%0,%1,%2,%3}, [%4];"
                 : "=r"(r[0]), "=r"(r[1]), "=r"(r[2]), "=r"(r[3]) : "r"(addr));
}
__device__ __forceinline__ void ldmx4t(uint32_t* r, uint32_t addr) {
    asm volatile("ldmatrix.sync.aligned.m8n8.x4.trans.shared.b16 {%0,%1,%2,%3}, [%4];"
                 : "=r"(r[0]), "=r"(r[1]), "=r"(r[2]), "=r"(r[3]) : "r"(addr));
}
__device__ __forceinline__ void mma16816(float* c, const uint32_t* a, const uint32_t* b) {
    asm volatile("mma.sync.aligned.m16n8k16.row.col.f32.f16.f16.f32 "
                 "{%0,%1,%2,%3}, {%4,%5,%6,%7}, {%8,%9}, {%0,%1,%2,%3};"
                 : "+f"(c[0]), "+f"(c[1]), "+f"(c[2]), "+f"(c[3])
                 : "r"(a[0]), "r"(a[1]), "r"(a[2]), "r"(a[3]), "r"(b[0]), "r"(b[1]));
}
#define CP_ASYNC16(smem, gmem) \
    asm volatile("cp.async.cg.shared.global [%0], [%1], 16;" \
                 :: "r"(smem), "l"(gmem) : "memory")
#define CP_COMMIT() asm volatile("cp.async.commit_group;" ::: "memory")
#define CP_WAIT0()  asm volatile("cp.async.wait_group 0;" ::: "memory")
#define CP_WAIT1()  asm volatile("cp.async.wait_group 1;" ::: "memory")

// ===================== mma.sync fp16 GEMM body =============================
// CTA tile 128x256x32, 8 warps (2m x 4n), warp tile 64x64.
// 3-stage cp.async ring + register fragment double-buffering.
#define TM 128
#define TN 256
#define KC 32
#define PAD 40
#define A_STAGE (TM * PAD * 2)               // 10240 B
#define B_STAGE (TN * PAD * 2)               // 20480 B
#define GEMM_SMEM (3 * (A_STAGE + B_STAGE))  // 92160 B

__device__ __forceinline__ void gemm_body(
    const __half* __restrict__ A, const __half* __restrict__ Bt,
    const float* __restrict__ bias, float* __restrict__ outf,
    __half* __restrict__ outh, int N, int K, int act,
    int m0, int n0, uint32_t sbase)
{
    #define SA_ADDR(st, r, c) (sbase + (uint32_t)(st) * A_STAGE + (uint32_t)((r) * PAD + (c)) * 2)
    #define SB_ADDR(st, r, c) (sbase + 3u * A_STAGE + (uint32_t)(st) * B_STAGE + (uint32_t)((r) * PAD + (c)) * 2)

    const int tid  = threadIdx.x;
    const int lane = tid & 31;
    const int wid  = tid >> 5;
    const int wm   = wid & 1;
    const int wn   = wid >> 1;

    float acc[4][8][4];
    #pragma unroll
    for (int i = 0; i < 4; i++)
        #pragma unroll
        for (int j = 0; j < 8; j++)
            #pragma unroll
            for (int q = 0; q < 4; q++) acc[i][j][q] = 0.f;

    const int r0c = tid >> 1;
    const int j0c = (tid & 1) * 2;
    const int nch = K / KC;

    #define ISSUE_CHUNK(cc_, stg_) do {                                              \
        const __half* Ag_ = A  + (size_t)m0 * K + (cc_) * KC;                        \
        const __half* Bg_ = Bt + (size_t)n0 * K + (cc_) * KC;                        \
        _Pragma("unroll")                                                            \
        for (int j = 0; j < 2; j++)                                                  \
            CP_ASYNC16(SA_ADDR(stg_, r0c, (j0c + j) * 8), Ag_ + (size_t)r0c * K + (j0c + j) * 8); \
        _Pragma("unroll")                                                            \
        for (int h = 0; h < 2; h++) {                                                \
            int rb_ = r0c + h * 128;                                                 \
            _Pragma("unroll")                                                        \
            for (int j = 0; j < 2; j++)                                              \
                CP_ASYNC16(SB_ADDR(stg_, rb_, (j0c + j) * 8), Bg_ + (size_t)rb_ * K + (j0c + j) * 8); \
        }                                                                            \
    } while (0)

    #define LDFRAGS(stg_, ks_, AF, BF) do {                                          \
        _Pragma("unroll")                                                            \
        for (int mi = 0; mi < 4; mi++) {                                             \
            int r_  = wm * 64 + mi * 16 + (lane & 15);                               \
            int cc_ = (ks_) * 16 + ((lane >> 4) << 3);                               \
            ldmx4((AF)[mi], SA_ADDR(stg_, r_, cc_));                                 \
        }                                                                            \
        _Pragma("unroll")                                                            \
        for (int nj = 0; nj < 4; nj++) {                                             \
            int r_  = wn * 64 + nj * 16 + ((lane & 7) | ((lane & 16) >> 1));         \
            int cc_ = (ks_) * 16 + (((lane >> 3) & 1) << 3);                         \
            ldmx4((BF)[nj], SB_ADDR(stg_, r_, cc_));                                 \
        }                                                                            \
    } while (0)

    #define MMASET(AF, BF) do {                                                      \
        _Pragma("unroll")                                                            \
        for (int mi = 0; mi < 4; mi++)                                               \
            _Pragma("unroll")                                                        \
            for (int nj = 0; nj < 8; nj++)                                           \
                mma16816(acc[mi][nj], (AF)[mi], &(BF)[nj >> 1][(nj & 1) * 2]);       \
    } while (0)

    ISSUE_CHUNK(0, 0); CP_COMMIT();
    ISSUE_CHUNK(1, 1); CP_COMMIT();
    CP_WAIT1();
    __syncthreads();

    uint32_t afr0[4][4], bfr0[4][4], afr1[4][4], bfr1[4][4];
    LDFRAGS(0, 0, afr0, bfr0);

    int st = 0, stw = 2;
    for (int c = 0; c < nch; c++) {
        if (c + 2 < nch) ISSUE_CHUNK(c + 2, stw);
        CP_COMMIT();

        LDFRAGS(st, 1, afr1, bfr1);
        MMASET(afr0, bfr0);

        if (c + 1 < nch) {
            CP_WAIT1();
            __syncthreads();
            const int nst = (st == 2) ? 0 : st + 1;
            LDFRAGS(nst, 0, afr0, bfr0);
        }
        MMASET(afr1, bfr1);

        st  = (st  == 2) ? 0 : st  + 1;
        stw = (stw == 2) ? 0 : stw + 1;
    }

    #pragma unroll
    for (int mi = 0; mi < 4; mi++) {
        #pragma unroll
        for (int rr = 0; rr < 2; rr++) {
            const int row = m0 + wm * 64 + mi * 16 + rr * 8 + (lane >> 2);
            #pragma unroll
            for (int nj = 0; nj < 8; nj++) {
                const int col = n0 + wn * 64 + nj * 8 + (lane & 3) * 2;
                float v0 = acc[mi][nj][rr * 2 + 0] + bias[col];
                float v1 = acc[mi][nj][rr * 2 + 1] + bias[col + 1];
                if (act) {
                    v0 = 0.5f * v0 * (1.0f + erff(v0 * 0.70710678118654752f));
                    v1 = 0.5f * v1 * (1.0f + erff(v1 * 0.70710678118654752f));
                }
                if (outf)
                    *(float2*)(outf + (size_t)row * N + col) = make_float2(v0, v1);
                if (outh)
                    *(__half2*)(outh + (size_t)row * N + col) = __floats2half2_rn(v0, v1);
            }
        }
    }
    #undef SA_ADDR
    #undef SB_ADDR
    #undef ISSUE_CHUNK
    #undef LDFRAGS
    #undef MMASET
}

__global__ void __launch_bounds__(256)
gemm_tc(const __half* __restrict__ A, const __half* __restrict__ Bt,
        const float* __restrict__ bias, float* __restrict__ outf,
        __half* __restrict__ outh, int M, int N, int K, int act)
{
    extern __shared__ char dynsm[];
    gemm_body(A, Bt, bias, outf, outh, N, K, act,
              blockIdx.y * TM, blockIdx.x * TN, smem_u32(dynsm));
}

// ================= fused flash attention (fp16 mma) ========================
// 128 Q rows per CTA, 8 warps (16 rows each), 256 threads. K tiles of 64.
// Base-2 softmax: Q pre-scaled by 0.125*log2(e); exp == single MUFU ex2.
__global__ void __launch_bounds__(256, 2)
flash_kernel(const __half* __restrict__ Qp, const __half* __restrict__ Kp,
             const __half* __restrict__ Vp, __half* __restrict__ Op,
             int qrs, int krs, int qhs, int khs, int kadd, int vadd, int causal)
{
    __shared__ __align__(16) __half sQ[128][72];
    __shared__ __align__(16) __half sK[2][64][72];
    __shared__ __align__(16) __half sV[2][64][72];

    const int tid  = threadIdx.x;
    const int lane = tid & 31;
    const int warp = tid >> 5;
    const int bh = blockIdx.y;
    const int b  = bh >> 4;
    const int h  = bh & 15;
    const int q0 = blockIdx.x * 128;

    const __half* Qb = Qp + (size_t)(b * S_ + q0) * qrs + h * qhs;
    const __half* Kb = Kp + (size_t)(b * S_) * krs + h * khs + kadd;
    const __half* Vb = Vp + (size_t)(b * S_) * krs + h * khs + vadd;

    const __half2 scq = __float2half2_rn(0.125f * 1.44269504088896f);
    #pragma unroll
    for (int i = 0; i < 4; i++) {
        int ch = tid + i * 256;
        int r = ch >> 3, j = ch & 7;
        uint4 u = *(const uint4*)(Qb + (size_t)r * qrs + j * 8);
        __half2* hp = (__half2*)&u;
        #pragma unroll
        for (int q = 0; q < 4; q++) hp[q] = __hmul2(hp[q], scq);
        *(uint4*)&sQ[r][j * 8] = u;
    }
    #pragma unroll
    for (int i = 0; i < 2; i++) {
        int ch = tid + i * 256;
        int r = ch >> 3, j = ch & 7;
        CP_ASYNC16(smem_u32(&sK[0][r][j * 8]), Kb + (size_t)r * krs + j * 8);
        CP_ASYNC16(smem_u32(&sV[0][r][j * 8]), Vb + (size_t)r * krs + j * 8);
    }
    CP_COMMIT();

    uint32_t qf[4][4];
    float m0 = -1e30f, m1 = -1e30f, l0 = 0.f, l1 = 0.f;
    float o[8][4];
    #pragma unroll
    for (int nj = 0; nj < 8; nj++)
        #pragma unroll
        for (int q = 0; q < 4; q++) o[nj][q] = 0.f;

    const int nkt = causal ? (2 * (blockIdx.x + 1)) : (S_ / 64);

    for (int kt = 0; kt < nkt; kt++) {
        CP_WAIT0();
        __syncthreads();

        if (kt == 0) {
            #pragma unroll
            for (int ks = 0; ks < 4; ks++) {
                int r  = warp * 16 + (lane & 15);
                int cc = ks * 16 + ((lane >> 4) << 3);
                ldmx4(qf[ks], smem_u32(&sQ[r][cc]));
            }
        }
        if (kt + 1 < nkt) {
            const int nb = (kt + 1) & 1;
            #pragma unroll
            for (int i = 0; i < 2; i++) {
                int ch = tid + i * 256;
                int r = ch >> 3, j = ch & 7;
                CP_ASYNC16(smem_u32(&sK[nb][r][j * 8]), Kb + (size_t)((kt + 1) * 64 + r) * krs + j * 8);
                CP_ASYNC16(smem_u32(&sV[nb][r][j * 8]), Vb + (size_t)((kt + 1) * 64 + r) * krs + j * 8);
            }
            CP_COMMIT();
        }
        const int cb = kt & 1;

        float s[8][4];
        #pragma unroll
        for (int nj = 0; nj < 8; nj++)
            #pragma unroll
            for (int q = 0; q < 4; q++) s[nj][q] = 0.f;

        #pragma unroll
        for (int ks = 0; ks < 4; ks++) {
            #pragma unroll
            for (int nj2 = 0; nj2 < 4; nj2++) {
                uint32_t bf[4];
                int r  = nj2 * 16 + ((lane & 7) | ((lane & 16) >> 1));
                int cc = ks * 16 + (((lane >> 3) & 1) << 3);
                ldmx4(bf, smem_u32(&sK[cb][r][cc]));
                mma16816(s[2 * nj2],     qf[ks], &bf[0]);
                mma16816(s[2 * nj2 + 1], qf[ks], &bf[2]);
            }
        }

        if (causal && (kt * 64 + 63 > q0 + warp * 16)) {
            int rl = q0 + warp * 16 + (lane >> 2);
            int c0 = kt * 64 + (lane & 3) * 2;
            #pragma unroll
            for (int nj = 0; nj < 8; nj++) {
                int kg = c0 + nj * 8;
                if (kg     > rl)     s[nj][0] = -1e30f;
                if (kg + 1 > rl)     s[nj][1] = -1e30f;
                if (kg     > rl + 8) s[nj][2] = -1e30f;
                if (kg + 1 > rl + 8) s[nj][3] = -1e30f;
            }
        }

        float mx0 = -1e30f, mx1 = -1e30f;
        #pragma unroll
        for (int nj = 0; nj < 8; nj++) {
            mx0 = fmaxf(mx0, fmaxf(s[nj][0], s[nj][1]));
            mx1 = fmaxf(mx1, fmaxf(s[nj][2], s[nj][3]));
        }
        mx0 = fmaxf(mx0, __shfl_xor_sync(~0u, mx0, 1));
        mx0 = fmaxf(mx0, __shfl_xor_sync(~0u, mx0, 2));
        mx1 = fmaxf(mx1, __shfl_xor_sync(~0u, mx1, 1));
        mx1 = fmaxf(mx1, __shfl_xor_sync(~0u, mx1, 2));

        float nm0 = fmaxf(m0, mx0), nm1 = fmaxf(m1, mx1);
        float sc0 = ex2f(m0 - nm0), sc1 = ex2f(m1 - nm1);
        m0 = nm0; m1 = nm1;
        l0 *= sc0; l1 *= sc1;
        #pragma unroll
        for (int nj = 0; nj < 8; nj++) {
            o[nj][0] *= sc0; o[nj][1] *= sc0;
            o[nj][2] *= sc1; o[nj][3] *= sc1;
        }

        uint32_t pk[8][2];
        float rs0 = 0.f, rs1 = 0.f;
        #pragma unroll
        for (int nj = 0; nj < 8; nj++) {
            float p0 = ex2f(s[nj][0] - m0), p1 = ex2f(s[nj][1] - m0);
            float p2 = ex2f(s[nj][2] - m1), p3 = ex2f(s[nj][3] - m1);
            rs0 += p0 + p1; rs1 += p2 + p3;
            __half2 hA = __floats2half2_rn(p0, p1);
            __half2 hB = __floats2half2_rn(p2, p3);
            pk[nj][0] = *(uint32_t*)&hA;
            pk[nj][1] = *(uint32_t*)&hB;
        }
        l0 += rs0; l1 += rs1;

        #pragma unroll
        for (int t = 0; t < 4; t++) {
            uint32_t a[4] = { pk[2 * t][0], pk[2 * t][1], pk[2 * t + 1][0], pk[2 * t + 1][1] };
            #pragma unroll
            for (int nj2 = 0; nj2 < 4; nj2++) {
                uint32_t bf[4];
                int r  = t * 16 + (lane & 15);
                int cc = nj2 * 16 + ((lane >> 4) << 3);
                ldmx4t(bf, smem_u32(&sV[cb][r][cc]));
                mma16816(o[2 * nj2],     a, &bf[0]);
                mma16816(o[2 * nj2 + 1], a, &bf[2]);
            }
        }
    }

    l0 += __shfl_xor_sync(~0u, l0, 1);
    l0 += __shfl_xor_sync(~0u, l0, 2);
    l1 += __shfl_xor_sync(~0u, l1, 1);
    l1 += __shfl_xor_sync(~0u, l1, 2);
    float inv0 = 1.f / l0, inv1 = 1.f / l1;

    const int row0 = q0 + warp * 16 + (lane >> 2);
    #pragma unroll
    for (int nj = 0; nj < 8; nj++) {
        int col = h * 64 + nj * 8 + (lane & 3) * 2;
        *(__half2*)(Op + (size_t)(b * S_ + row0) * D_ + col) =
            __floats2half2_rn(o[nj][0] * inv0, o[nj][1] * inv0);
        *(__half2*)(Op + (size_t)(b * S_ + row0 + 8) * D_ + col) =
            __floats2half2_rn(o[nj][2] * inv1, o[nj][3] * inv1);
    }
}

// -------- fused residual-add + LayerNorm (fp32 resid + fp16 y input) -------
__global__ __launch_bounds__(256)
void add_ln_kernel(const float* __restrict__ resid, const __half* __restrict__ y,
                   const float* __restrict__ g, const float* __restrict__ be,
                   float* __restrict__ out, __half* __restrict__ out16)
{
    const size_t base = (size_t)blockIdx.x * 1024;
    const int t = threadIdx.x;
    const int c0 = t * 4;
    __shared__ float red[8];

    float4 r4 = *(const float4*)(resid + base + c0);
    __half2 ya = ((const __half2*)(y + base + c0))[0];
    __half2 yb = ((const __half2*)(y + base + c0))[1];
    float v[4];
    v[0] = r4.x + __low2float(ya);
    v[1] = r4.y + __high2float(ya);
    v[2] = r4.z + __low2float(yb);
    v[3] = r4.w + __high2float(yb);

    float s = v[0] + v[1] + v[2] + v[3];
    #pragma unroll
    for (int o = 16; o; o >>= 1) s += __shfl_xor_sync(~0u, s, o);
    if ((t & 31) == 0) red[t >> 5] = s;
    __syncthreads();
    float tot = 0;
    #pragma unroll
    for (int i = 0; i < 8; i++) tot += red[i];
    float mean = tot * (1.0f / 1024.0f);
    __syncthreads();

    float vs = 0;
    #pragma unroll
    for (int i = 0; i < 4; i++) { float d = v[i] - mean; vs += d * d; }
    #pragma unroll
    for (int o = 16; o; o >>= 1) vs += __shfl_xor_sync(~0u, vs, o);
    if ((t & 31) == 0) red[t >> 5] = vs;
    __syncthreads();
    tot = 0;
    #pragma unroll
    for (int i = 0; i < 8; i++) tot += red[i];
    float inv = rsqrtf(tot * (1.0f / 1024.0f) + 1e-5f);

    float4 g4  = *(const float4*)(g  + c0);
    float4 be4 = *(const float4*)(be + c0);
    float r0 = g4.x * (v[0] - mean) * inv + be4.x;
    float r1 = g4.y * (v[1] - mean) * inv + be4.y;
    float r2 = g4.z * (v[2] - mean) * inv + be4.z;
    float r3 = g4.w * (v[3] - mean) * inv + be4.w;
    *(float4*)(out + base + c0) = make_float4(r0, r1, r2, r3);
    if (out16) {
        ((__half2*)(out16 + base + c0))[0] = __floats2half2_rn(r0, r1);
        ((__half2*)(out16 + base + c0))[1] = __floats2half2_rn(r2, r3);
    }
}

// ================================ launch ===================================
extern "C" void kernel_launch(void* const* d_in, const int* in_sizes, int n_in,
                              void* d_out, int out_size)
{
    const float* x      = (const float*)d_in[0];
    const float* enc_x  = (const float*)d_in[1];
    const float* w_qkv  = (const float*)d_in[2];
    const float* b_qkv  = (const float*)d_in[3];
    const float* w_sa_o = (const float*)d_in[4];
    const float* b_sa_o = (const float*)d_in[5];
    const float* w_q    = (const float*)d_in[6];
    const float* b_q    = (const float*)d_in[7];
    const float* w_k    = (const float*)d_in[8];
    const float* b_k    = (const float*)d_in[9];
    const float* w_v    = (const float*)d_in[10];
    const float* b_v    = (const float*)d_in[11];
    const float* w_ca_o = (const float*)d_in[12];
    const float* b_ca_o = (const float*)d_in[13];
    const float* w1     = (const float*)d_in[14];
    const float* b1     = (const float*)d_in[15];
    const float* w2     = (const float*)d_in[16];
    const float* b2     = (const float*)d_in[17];
    const float* g1     = (const float*)d_in[18];
    const float* be1    = (const float*)d_in[19];
    const float* g2     = (const float*)d_in[20];
    const float* be2    = (const float*)d_in[21];
    const float* g3     = (const float*)d_in[22];
    const float* be3    = (const float*)d_in[23];
    float* out = (float*)d_out;

    float *p_h1, *p_h2;
    cudaGetSymbolAddress((void**)&p_h1,   g_h1);
    cudaGetSymbolAddress((void**)&p_h2,   g_h2);

    __half *p_y16, *p_x16, *p_ex16, *p_qkv16, *p_attn16, *p_h16, *p_q16, *p_k16, *p_v16, *p_f116;
    __half *p_wqkvT, *p_wsaoT, *p_wqT, *p_wkT, *p_wvT, *p_wcaoT, *p_w1T, *p_w2T;
    cudaGetSymbolAddress((void**)&p_y16,    g_y16);
    cudaGetSymbolAddress((void**)&p_x16,    g_x16);
    cudaGetSymbolAddress((void**)&p_ex16,   g_ex16);
    cudaGetSymbolAddress((void**)&p_qkv16,  g_qkv16);
    cudaGetSymbolAddress((void**)&p_attn16, g_attn16);
    cudaGetSymbolAddress((void**)&p_h16,    g_h16);
    cudaGetSymbolAddress((void**)&p_q16,    g_q16);
    cudaGetSymbolAddress((void**)&p_k16,    g_k16);
    cudaGetSymbolAddress((void**)&p_v16,    g_v16);
    cudaGetSymbolAddress((void**)&p_f116,   g_f116);
    cudaGetSymbolAddress((void**)&p_wqkvT,  g_wqkvT);
    cudaGetSymbolAddress((void**)&p_wsaoT,  g_wsaoT);
    cudaGetSymbolAddress((void**)&p_wqT,    g_wqT);
    cudaGetSymbolAddress((void**)&p_wkT,    g_wkT);
    cudaGetSymbolAddress((void**)&p_wvT,    g_wvT);
    cudaGetSymbolAddress((void**)&p_wcaoT,  g_wcaoT);
    cudaGetSymbolAddress((void**)&p_w1T,    g_w1T);
    cudaGetSymbolAddress((void**)&p_w2T,    g_w2T);

    cudaFuncSetAttribute(gemm_tc, cudaFuncAttributeMaxDynamicSharedMemorySize, GEMM_SMEM);

    const dim3 blk256(256);
    const dim3 fgrd(S_ / 128, B_ * H_);

    // fork stream + events (created per call; intentionally not destroyed,
    // kernel_launch only runs a handful of times and these hold no device mem)
    cudaStream_t s2;
    cudaStreamCreateWithFlags(&s2, cudaStreamNonBlocking);
    cudaEvent_t evPrep, evKV;
    cudaEventCreateWithFlags(&evPrep, cudaEventDisableTiming);
    cudaEventCreateWithFlags(&evKV,  cudaEventDisableTiming);

    // ---- single fused prep: all weight transposes + input converts ----
    prep_kernel<<<PREP_BLOCKS, 1024>>>(w_qkv, w_sa_o, w_q, w_k, w_v, w_ca_o, w1, w2,
                                       x, enc_x,
                                       p_wqkvT, p_wsaoT, p_wqT, p_wkT, p_wvT, p_wcaoT,
                                       p_w1T, p_w2T, p_x16, p_ex16);
    cudaEventRecord(evPrep, 0);
    cudaStreamWaitEvent(s2, evPrep, 0);

    // ---- side stream: cross-attention K and V projections ----
    gemm_tc<<<dim3(D_ / TN, MROWS / TM), 256, GEMM_SMEM, s2>>>(
        p_ex16, p_wkT, b_k, (float*)0, p_k16, B_ * E_, D_, D_, 0);
    gemm_tc<<<dim3(D_ / TN, MROWS / TM), 256, GEMM_SMEM, s2>>>(
        p_ex16, p_wvT, b_v, (float*)0, p_v16, B_ * E_, D_, D_, 0);
    cudaEventRecord(evKV, s2);

    // ---- main stream: self-attention chain ----
    gemm_tc<<<dim3(3 * D_ / TN, MROWS / TM), 256, GEMM_SMEM>>>(
        p_x16, p_wqkvT, b_qkv, (float*)0, p_qkv16, MROWS, 3 * D_, D_, 0);
    flash_kernel<<<fgrd, 256>>>(p_qkv16, p_qkv16, p_qkv16, p_attn16,
                                3 * D_, 3 * D_, 192, 192, 64, 128, 1);
    gemm_tc<<<dim3(D_ / TN, MROWS / TM), 256, GEMM_SMEM>>>(
        p_attn16, p_wsaoT, b_sa_o, (float*)0, p_y16, MROWS, D_, D_, 0);
    add_ln_kernel<<<MROWS, blk256>>>(x, p_y16, g1, be1, p_h1, p_h16);

    // ---- cross-attention ----
    gemm_tc<<<dim3(D_ / TN, MROWS / TM), 256, GEMM_SMEM>>>(
        p_h16, p_wqT, b_q, (float*)0, p_q16, MROWS, D_, D_, 0);
    cudaStreamWaitEvent(0, evKV, 0);   // join K/V before cross flash
    flash_kernel<<<fgrd, 256>>>(p_q16, p_k16, p_v16, p_attn16,
                                D_, D_, 64, 64, 0, 0, 0);
    gemm_tc<<<dim3(D_ / TN, MROWS / TM), 256, GEMM_SMEM>>>(
        p_attn16, p_wcaoT, b_ca_o, (float*)0, p_y16, MROWS, D_, D_, 0);
    add_ln_kernel<<<MROWS, blk256>>>(p_h1, p_y16, g2, be2, p_h2, p_h16);

    // ---- FFN ----
    gemm_tc<<<dim3(DFF_ / TN, MROWS / TM), 256, GEMM_SMEM>>>(
        p_h16, p_w1T, b1, (float*)0, p_f116, MROWS, DFF_, D_, 1);
    gemm_tc<<<dim3(D_ / TN, MROWS / TM), 256, GEMM_SMEM>>>(
        p_f116, p_w2T, b2, (float*)0, p_y16, MROWS, D_, DFF_, 0);
    add_ln_kernel<<<MROWS, blk256>>>(p_h2, p_y16, g3, be3, out, (__half*)0);
}